// round 3
// baseline (speedup 1.0000x reference)
#include <cuda_runtime.h>
#include <math.h>

#define N_TOK 8192
#define D 256
#define BM 64
#define BN 64
#define TPB 256
#define TSTRIDE 68   // padded stride (floats) for transposed smem tiles; 16B-aligned, conflict-free
#define ESTRIDE 68   // padded stride for E tile (4*68 mod 32 = 16 -> ty-halves hit distinct banks)

// Smem budget check: must fit under the 227 KB sm_100 opt-in limit.
static_assert((2 * D * TSTRIDE + BN * D + BM * ESTRIDE) * sizeof(float) <= 232448,
              "flash kernel smem exceeds sm_100 limit");

// Scratch (device globals; no runtime allocation allowed)
__device__ float g_q[N_TOK * D];
__device__ float g_k[N_TOK * D];
__device__ float g_attn[N_TOK * D];
__device__ float g_sq[N_TOK];
__device__ float g_feat[N_TOK];

// Load a 64-row x 256-col fp32 tile, transposed, into smem [D][TSTRIDE].
__device__ __forceinline__ void load_tile_T(const float* __restrict__ src, float* dst,
                                            int row0, int tid) {
    for (int v = tid; v < BM * (D / 4); v += TPB) {
        int m  = v >> 6;        // row within tile
        int dv = v & 63;        // float4 index within row
        float4 t = reinterpret_cast<const float4*>(src + (row0 + m) * D)[dv];
        int d = dv * 4;
        dst[(d + 0) * TSTRIDE + m] = t.x;
        dst[(d + 1) * TSTRIDE + m] = t.y;
        dst[(d + 2) * TSTRIDE + m] = t.z;
        dst[(d + 3) * TSTRIDE + m] = t.w;
    }
}

// ---------------------------------------------------------------------------
// Kernel 1: q = states @ Wq, k = states @ Wk   (blockIdx.z selects which)
// ---------------------------------------------------------------------------
__global__ void gemm_qk_kernel(const float* __restrict__ x,
                               const float* __restrict__ Wq,
                               const float* __restrict__ Wk) {
    extern __shared__ float sm[];
    float* As = sm;                    // [D][TSTRIDE] transposed states tile
    float* Bs = sm + D * TSTRIDE;      // [D][BN] natural layout W tile

    const float* W   = (blockIdx.z == 0) ? Wq : Wk;
    float*       out = (blockIdx.z == 0) ? g_q : g_k;

    int mtile = blockIdx.y * BM;
    int ntile = blockIdx.x * BN;
    int tid = threadIdx.x;

    load_tile_T(x, As, mtile, tid);
    for (int v = tid; v < D * (BN / 4); v += TPB) {
        int kk = v >> 4;
        int nv = v & 15;
        reinterpret_cast<float4*>(Bs + kk * BN)[nv] =
            reinterpret_cast<const float4*>(W + kk * D + ntile)[nv];
    }
    __syncthreads();

    int ty = tid >> 4, tx = tid & 15;
    int m0 = ty * 4, n0 = tx * 4;
    float c[4][4] = {};

    #pragma unroll 8
    for (int kk = 0; kk < D; kk++) {
        float4 a = *reinterpret_cast<const float4*>(As + kk * TSTRIDE + m0);
        float4 b = *reinterpret_cast<const float4*>(Bs + kk * BN + n0);
        float av[4] = {a.x, a.y, a.z, a.w};
        float bv[4] = {b.x, b.y, b.z, b.w};
        #pragma unroll
        for (int i = 0; i < 4; i++)
            #pragma unroll
            for (int j = 0; j < 4; j++)
                c[i][j] = fmaf(av[i], bv[j], c[i][j]);
    }

    #pragma unroll
    for (int i = 0; i < 4; i++) {
        float4 r;
        r.x = c[i][0]; r.y = c[i][1]; r.z = c[i][2]; r.w = c[i][3];
        *reinterpret_cast<float4*>(out + (mtile + m0 + i) * D + ntile + n0) = r;
    }
}

// ---------------------------------------------------------------------------
// Kernel 2: flash-style attention (no max subtraction; logits/16 ~ N(0,1),
// bounded ~|6| over 64M samples -> exp safe in fp32).
//   attn[m,:] = (sum_j exp(q_m.k_j/16) x_j) / (sum_j exp(q_m.k_j/16))
// Epilogue also emits sq[m] = ||attn_m||^2.
// Stage-2 column ownership is interleaved: thread tx owns d-cols
// {tx*4 + v*64 : v=0..3} -> conflict-free LDS.128 (phase stride = 4 words).
// ---------------------------------------------------------------------------
__global__ void flash_attn_kernel(const float* __restrict__ x) {
    extern __shared__ float sm[];
    float* Qs = sm;                         // [D][TSTRIDE] transposed q tile (resident)
    float* Ks = Qs + D * TSTRIDE;           // [D][TSTRIDE] transposed k tile (per j-tile)
    float* Xs = Ks + D * TSTRIDE;           // [BN][D] natural states tile
    float* Es = Xs + BN * D;                // [BM][ESTRIDE] exp(S) tile

    int mtile = blockIdx.x * BM;
    int tid = threadIdx.x;
    int ty = tid >> 4, tx = tid & 15;
    int m0 = ty * 4, n0 = tx * 4;
    int dc0 = tx * 4;                       // base of interleaved column ownership

    load_tile_T(g_q, Qs, mtile, tid);

    float acc[4][16] = {};
    float den[4] = {};

    for (int jt = 0; jt < N_TOK / BN; jt++) {
        __syncthreads();   // protect Ks/Xs/Es against previous iteration's readers
        int jbase = jt * BN;

        load_tile_T(g_k, Ks, jbase, tid);
        {   // states tile: contiguous rows -> straight float4 copy
            const float4* src = reinterpret_cast<const float4*>(x + jbase * D);
            float4* dst = reinterpret_cast<float4*>(Xs);
            for (int v = tid; v < BN * (D / 4); v += TPB) dst[v] = src[v];
        }
        __syncthreads();

        // Stage 1: S = Q @ K^T (64x64 tile, 4x4 per thread)
        float cf[4][4] = {};
        #pragma unroll 8
        for (int kk = 0; kk < D; kk++) {
            float4 a = *reinterpret_cast<const float4*>(Qs + kk * TSTRIDE + m0);
            float4 b = *reinterpret_cast<const float4*>(Ks + kk * TSTRIDE + n0);
            float av[4] = {a.x, a.y, a.z, a.w};
            float bv[4] = {b.x, b.y, b.z, b.w};
            #pragma unroll
            for (int i = 0; i < 4; i++)
                #pragma unroll
                for (int j = 0; j < 4; j++)
                    cf[i][j] = fmaf(av[i], bv[j], cf[i][j]);
        }

        // exp(S/16) -> Es
        #pragma unroll
        for (int i = 0; i < 4; i++) {
            float4 e;
            e.x = __expf(cf[i][0] * 0.0625f);
            e.y = __expf(cf[i][1] * 0.0625f);
            e.z = __expf(cf[i][2] * 0.0625f);
            e.w = __expf(cf[i][3] * 0.0625f);
            *reinterpret_cast<float4*>(Es + (m0 + i) * ESTRIDE + n0) = e;
        }
        __syncthreads();

        // Stage 2: acc += E @ X, den += rowsum(E).
        #pragma unroll 2
        for (int j = 0; j < BN; j++) {
            float e[4];
            #pragma unroll
            for (int i = 0; i < 4; i++) {
                e[i] = Es[(m0 + i) * ESTRIDE + j];
                den[i] += e[i];
            }
            const float* xr = Xs + j * D;
            #pragma unroll
            for (int v = 0; v < 4; v++) {
                float4 xv = *reinterpret_cast<const float4*>(xr + dc0 + v * 64);
                #pragma unroll
                for (int i = 0; i < 4; i++) {
                    acc[i][4 * v + 0] = fmaf(e[i], xv.x, acc[i][4 * v + 0]);
                    acc[i][4 * v + 1] = fmaf(e[i], xv.y, acc[i][4 * v + 1]);
                    acc[i][4 * v + 2] = fmaf(e[i], xv.z, acc[i][4 * v + 2]);
                    acc[i][4 * v + 3] = fmaf(e[i], xv.w, acc[i][4 * v + 3]);
                }
            }
        }
    }

    // Epilogue: normalize, write attn, and compute sq = ||attn||^2.
    float sq[4] = {};
    #pragma unroll
    for (int i = 0; i < 4; i++) {
        float rinv = 1.0f / den[i];
        float* op = g_attn + (mtile + m0 + i) * D;
        #pragma unroll
        for (int v = 0; v < 4; v++) {
            float4 o;
            o.x = acc[i][4 * v + 0] * rinv;
            o.y = acc[i][4 * v + 1] * rinv;
            o.z = acc[i][4 * v + 2] * rinv;
            o.w = acc[i][4 * v + 3] * rinv;
            sq[i] += o.x * o.x + o.y * o.y + o.z * o.z + o.w * o.w;
            *reinterpret_cast<float4*>(op + dc0 + v * 64) = o;
        }
    }
    // reduce sq across the 16 tx lanes owning this row
    #pragma unroll
    for (int i = 0; i < 4; i++) {
        #pragma unroll
        for (int o = 8; o > 0; o >>= 1)
            sq[i] += __shfl_down_sync(0xffffffffu, sq[i], o, 16);
    }
    if (tx == 0) {
        #pragma unroll
        for (int i = 0; i < 4; i++)
            g_sq[mtile + m0 + i] = sq[i];
    }
}

// ---------------------------------------------------------------------------
// Kernel 3: feat[i] = mean_j exp(-max(sq_i + sq_j - 2*attn_i.attn_j, 0))
// Fused GEMM (attn @ attn^T tile) + RBF + row reduction. No N x N buffer.
// ---------------------------------------------------------------------------
__global__ void rbf_feat_kernel() {
    extern __shared__ float sm[];
    float* As  = sm;                    // [D][TSTRIDE] transposed attn rows (resident)
    float* Bs  = As + D * TSTRIDE;      // [D][TSTRIDE] transposed attn j-tile
    float* sqj = Bs + D * TSTRIDE;      // [BN]

    int mtile = blockIdx.x * BM;
    int tid = threadIdx.x;
    int ty = tid >> 4, tx = tid & 15;
    int m0 = ty * 4, n0 = tx * 4;

    load_tile_T(g_attn, As, mtile, tid);
    float sqi[4];
    #pragma unroll
    for (int i = 0; i < 4; i++) sqi[i] = g_sq[mtile + m0 + i];

    float fs[4] = {};

    for (int jt = 0; jt < N_TOK / BN; jt++) {
        __syncthreads();
        int jbase = jt * BN;
        load_tile_T(g_attn, Bs, jbase, tid);
        if (tid < BN) sqj[tid] = g_sq[jbase + tid];
        __syncthreads();

        float cf[4][4] = {};
        #pragma unroll 8
        for (int kk = 0; kk < D; kk++) {
            float4 a = *reinterpret_cast<const float4*>(As + kk * TSTRIDE + m0);
            float4 b = *reinterpret_cast<const float4*>(Bs + kk * TSTRIDE + n0);
            float av[4] = {a.x, a.y, a.z, a.w};
            float bv[4] = {b.x, b.y, b.z, b.w};
            #pragma unroll
            for (int i = 0; i < 4; i++)
                #pragma unroll
                for (int j = 0; j < 4; j++)
                    cf[i][j] = fmaf(av[i], bv[j], cf[i][j]);
        }

        #pragma unroll
        for (int j = 0; j < 4; j++) {
            float sj = sqj[n0 + j];
            #pragma unroll
            for (int i = 0; i < 4; i++) {
                float d2 = sqi[i] + sj - 2.0f * cf[i][j];
                fs[i] += __expf(-fmaxf(d2, 0.0f));   // GAMMA = 1
            }
        }
    }

    #pragma unroll
    for (int i = 0; i < 4; i++) {
        #pragma unroll
        for (int o = 8; o > 0; o >>= 1)
            fs[i] += __shfl_down_sync(0xffffffffu, fs[i], o, 16);
    }
    if (tx == 0) {
        #pragma unroll
        for (int i = 0; i < 4; i++)
            g_feat[mtile + m0 + i] = fs[i] * (1.0f / (float)N_TOK);
    }
}

// ---------------------------------------------------------------------------
// Kernel 4: MLP head  out[i] = b2 + sum_k relu(feat[i]*W1[k] + b1[k]) * W2[k]
// ---------------------------------------------------------------------------
__global__ void mlp_kernel(const float* __restrict__ W1, const float* __restrict__ b1,
                           const float* __restrict__ W2, const float* __restrict__ b2,
                           float* __restrict__ out) {
    __shared__ float w1[64], bb1[64], w2[64];
    int tid = threadIdx.x;
    if (tid < 64) { w1[tid] = W1[tid]; bb1[tid] = b1[tid]; w2[tid] = W2[tid]; }
    __syncthreads();
    int i = blockIdx.x * blockDim.x + tid;
    if (i >= N_TOK) return;
    float f = g_feat[i];
    float a = b2[0];
    #pragma unroll
    for (int k2 = 0; k2 < 64; k2++) {
        float h = fmaf(f, w1[k2], bb1[k2]);
        a = fmaf(fmaxf(h, 0.0f), w2[k2], a);
    }
    out[i] = a;
}

// ---------------------------------------------------------------------------
extern "C" void kernel_launch(void* const* d_in, const int* in_sizes, int n_in,
                              void* d_out, int out_size) {
    const float* states = (const float*)d_in[0];
    const float* Wq     = (const float*)d_in[1];
    const float* Wk     = (const float*)d_in[2];
    const float* W1     = (const float*)d_in[3];
    const float* b1     = (const float*)d_in[4];
    const float* W2     = (const float*)d_in[5];
    const float* b2     = (const float*)d_in[6];
    float* out = (float*)d_out;
    (void)in_sizes; (void)n_in; (void)out_size;

    size_t smem_gemm  = (size_t)(D * TSTRIDE + D * BN) * sizeof(float);
    size_t smem_flash = (size_t)(2 * D * TSTRIDE + BN * D + BM * ESTRIDE) * sizeof(float);
    size_t smem_rbf   = (size_t)(2 * D * TSTRIDE + BN) * sizeof(float);

    (void)cudaFuncSetAttribute(gemm_qk_kernel,    cudaFuncAttributeMaxDynamicSharedMemorySize, (int)smem_gemm);
    (void)cudaFuncSetAttribute(flash_attn_kernel, cudaFuncAttributeMaxDynamicSharedMemorySize, (int)smem_flash);
    (void)cudaFuncSetAttribute(rbf_feat_kernel,   cudaFuncAttributeMaxDynamicSharedMemorySize, (int)smem_rbf);

    dim3 g1(D / BN, N_TOK / BM, 2);
    gemm_qk_kernel<<<g1, TPB, smem_gemm>>>(states, Wq, Wk);
    flash_attn_kernel<<<N_TOK / BM, TPB, smem_flash>>>(states);
    rbf_feat_kernel<<<N_TOK / BM, TPB, smem_rbf>>>();
    mlp_kernel<<<N_TOK / TPB, TPB>>>(W1, b1, W2, b2, out);
}

// round 5
// speedup vs baseline: 2.9570x; 2.9570x over previous
#include <cuda_runtime.h>
#include <math.h>
#include <stdint.h>

#define N_TOK 8192
#define D 256
#define BM 64
#define BN 64
#define TPB 256
#define QSTR 260      // stride (u32) for natural [64][256] tf32 tiles; 260 mod 32 = 4 -> conflict-free frag reads
#define ESTR 68       // stride for E tile [64][64]
#define G4STR 272     // stride (u32) per d4-group for grouped-transposed tiles: [dim/4][64][4]; 272 mod 32 = 16

// flash smem: Qs + Ks + XsT + Es + red
static_assert((2 * BM * QSTR + (D / 4) * G4STR + BM * ESTR + 128) * 4 <= 232448, "flash smem");

__device__ float g_q[N_TOK * D];
__device__ float g_k[N_TOK * D];
__device__ float g_attn[N_TOK * D];
__device__ float g_sq[N_TOK];
__device__ float g_feat[N_TOK];

__device__ __forceinline__ uint32_t f2tf(float f) {
    uint32_t r;
    asm("cvt.rna.tf32.f32 %0, %1;" : "=r"(r) : "f"(f));
    return r;
}

__device__ __forceinline__ void mma_tf32(float c[4],
                                         uint32_t a0, uint32_t a1, uint32_t a2, uint32_t a3,
                                         uint32_t b0, uint32_t b1) {
    asm volatile(
        "mma.sync.aligned.m16n8k8.row.col.f32.tf32.tf32.f32 "
        "{%0,%1,%2,%3}, {%4,%5,%6,%7}, {%8,%9}, {%0,%1,%2,%3};"
        : "+f"(c[0]), "+f"(c[1]), "+f"(c[2]), "+f"(c[3])
        : "r"(a0), "r"(a1), "r"(a2), "r"(a3), "r"(b0), "r"(b1));
}

// Natural tile [64 rows][256 k] -> smem [64][QSTR] as tf32 (STS.128, conflict-free).
__device__ __forceinline__ void stage_nat(const float* __restrict__ src, uint32_t* dst,
                                          int row0, int tid) {
    for (int v = tid; v < BM * (D / 4); v += TPB) {
        int m = v >> 6, dv = (v & 63) * 4;
        float4 t = reinterpret_cast<const float4*>(src + (row0 + m) * D)[dv >> 2];
        uint4 u;
        u.x = f2tf(t.x); u.y = f2tf(t.y); u.z = f2tf(t.z); u.w = f2tf(t.w);
        *reinterpret_cast<uint4*>(dst + m * QSTR + dv) = u;
    }
}

// Transposed+grouped: src rows j=0..63, cols d=0..255 -> dst[(d>>2)*G4STR + j*4 + (d&3)].
// Coalesced global reads; STS.128 writes (one-time staging cost).
__device__ __forceinline__ void stage_Tg(const float* __restrict__ src, uint32_t* dst,
                                         int row0, int tid) {
    for (int v = tid; v < BM * (D / 4); v += TPB) {
        int m = v >> 6, dv = (v & 63) * 4;
        float4 t = reinterpret_cast<const float4*>(src + (row0 + m) * D)[dv >> 2];
        uint4 u;
        u.x = f2tf(t.x); u.y = f2tf(t.y); u.z = f2tf(t.z); u.w = f2tf(t.w);
        *reinterpret_cast<uint4*>(dst + (dv >> 2) * G4STR + m * 4) = u;
    }
}

// ---------------------------------------------------------------------------
// Kernel 1: q = states @ Wq, k = states @ Wk  (mma tf32; blockIdx.z selects)
// W staged as Wg[n][k] = W[k][ntile+n]  (same [row][QSTR] layout as Ks in flash;
// B fragment (k,n) read at n*QSTR + k, proven conflict-free).
// ---------------------------------------------------------------------------
__global__ void gemm_qk_kernel(const float* __restrict__ x,
                               const float* __restrict__ Wq,
                               const float* __restrict__ Wk) {
    extern __shared__ uint32_t sm[];
    uint32_t* Xs = sm;                  // [64][QSTR]
    uint32_t* Wg = sm + BM * QSTR;      // [64][QSTR] W^T tile

    const float* W   = (blockIdx.z == 0) ? Wq : Wk;
    float*       out = (blockIdx.z == 0) ? g_q : g_k;

    int mtile = blockIdx.y * BM;
    int ntile = blockIdx.x * BN;
    int tid = threadIdx.x, lane = tid & 31, w = tid >> 5;
    int wr = w >> 1, wc = w & 1, gid = lane >> 2, q = lane & 3;

    stage_nat(x, Xs, mtile, tid);
    // Wg[n][kk] = W[kk][ntile+n]: coalesced float4 global reads, scalar smem scatter.
    for (int v = tid; v < D * (BN / 4); v += TPB) {
        int kk = v >> 4, n4 = (v & 15) * 4;
        float4 t = *reinterpret_cast<const float4*>(W + kk * D + ntile + n4);
        Wg[(n4 + 0) * QSTR + kk] = f2tf(t.x);
        Wg[(n4 + 1) * QSTR + kk] = f2tf(t.y);
        Wg[(n4 + 2) * QSTR + kk] = f2tf(t.z);
        Wg[(n4 + 3) * QSTR + kk] = f2tf(t.w);
    }
    __syncthreads();

    float c[4][4] = {};
    int ar0 = (16 * wr + gid) * QSTR, ar1 = ar0 + 8 * QSTR;
    #pragma unroll
    for (int ks = 0; ks < 32; ks++) {
        int k0 = ks * 8;
        uint32_t a0 = Xs[ar0 + k0 + q], a1 = Xs[ar1 + k0 + q];
        uint32_t a2 = Xs[ar0 + k0 + q + 4], a3 = Xs[ar1 + k0 + q + 4];
        #pragma unroll
        for (int f = 0; f < 4; f++) {
            int b = (32 * wc + 8 * f + gid) * QSTR + k0 + q;
            mma_tf32(c[f], a0, a1, a2, a3, Wg[b], Wg[b + 4]);
        }
    }

    int r0 = mtile + 16 * wr + gid;
    #pragma unroll
    for (int f = 0; f < 4; f++) {
        int col = ntile + 32 * wc + 8 * f + 2 * q;
        *reinterpret_cast<float2*>(out + r0 * D + col)       = make_float2(c[f][0], c[f][1]);
        *reinterpret_cast<float2*>(out + (r0 + 8) * D + col) = make_float2(c[f][2], c[f][3]);
    }
}

// ---------------------------------------------------------------------------
// Kernel 2: flash attention, both GEMMs on mma tf32.
//   S = Q K^T (64x64/tile) -> E = exp(S/16) -> acc += E @ X, den += rowsum(E)
// Epilogue: attn = acc/den, sq = ||attn||^2.
// Warp (wr,wc): stage1 rows 16wr, cols 32wc; stage2 rows 16wr, d-cols 128wc.
// ---------------------------------------------------------------------------
__global__ void flash_attn_kernel(const float* __restrict__ x) {
    extern __shared__ uint32_t sm[];
    uint32_t* Qs  = sm;                       // [64][QSTR] resident q tile
    uint32_t* Ks  = Qs + BM * QSTR;           // [64][QSTR] k tile
    uint32_t* XsT = Ks + BM * QSTR;           // [64 d-groups][68][4] grouped x^T
    uint32_t* Es  = XsT + (D / 4) * G4STR;    // [64][ESTR] exp tile (tf32)
    float*    red = (float*)(Es + BM * ESTR); // [2][64] reductions

    int tid = threadIdx.x, lane = tid & 31, w = tid >> 5;
    int wr = w >> 1, wc = w & 1, gid = lane >> 2, q = lane & 3;
    int mtile = blockIdx.x * BM;

    stage_nat(g_q, Qs, mtile, tid);

    float acc[16][4];
    #pragma unroll
    for (int f = 0; f < 16; f++)
        acc[f][0] = acc[f][1] = acc[f][2] = acc[f][3] = 0.f;
    float den0 = 0.f, den1 = 0.f;

    int ar0 = (16 * wr + gid) * QSTR, ar1 = ar0 + 8 * QSTR;
    int er0 = (16 * wr + gid) * ESTR, er1 = er0 + 8 * ESTR;

    for (int jt = 0; jt < N_TOK / BN; jt++) {
        __syncthreads();
        int jb = jt * BN;
        stage_nat(g_k, Ks, jb, tid);
        stage_Tg(x, XsT, jb, tid);
        __syncthreads();

        // Stage 1: S = Q @ K^T
        float cS[4][4] = {};
        #pragma unroll
        for (int ks = 0; ks < 32; ks++) {
            int k0 = ks * 8;
            uint32_t a0 = Qs[ar0 + k0 + q], a1 = Qs[ar1 + k0 + q];
            uint32_t a2 = Qs[ar0 + k0 + q + 4], a3 = Qs[ar1 + k0 + q + 4];
            #pragma unroll
            for (int f = 0; f < 4; f++) {
                int b = (32 * wc + 8 * f + gid) * QSTR + k0 + q;
                mma_tf32(cS[f], a0, a1, a2, a3, Ks[b], Ks[b + 4]);
            }
        }

        // E = exp(S/16): accumulate den, store tf32 E for stage-2 A fragments
        #pragma unroll
        for (int f = 0; f < 4; f++) {
            float e0 = __expf(cS[f][0] * 0.0625f);
            float e1 = __expf(cS[f][1] * 0.0625f);
            float e2 = __expf(cS[f][2] * 0.0625f);
            float e3 = __expf(cS[f][3] * 0.0625f);
            den0 += e0 + e1; den1 += e2 + e3;
            int col = 32 * wc + 8 * f + 2 * q;
            Es[er0 + col]     = f2tf(e0);
            Es[er0 + col + 1] = f2tf(e1);
            Es[er1 + col]     = f2tf(e2);
            Es[er1 + col + 1] = f2tf(e3);
        }
        __syncthreads();

        // Stage 2: acc += E @ X  (A = E [64x64], B = X^T grouped, N = 256)
        #pragma unroll
        for (int ks = 0; ks < 8; ks++) {
            int k0 = ks * 8;
            uint32_t a0 = Es[er0 + k0 + q], a1 = Es[er1 + k0 + q];
            uint32_t a2 = Es[er0 + k0 + q + 4], a3 = Es[er1 + k0 + q + 4];
            #pragma unroll
            for (int f = 0; f < 16; f++) {
                int d = 128 * wc + 8 * f + gid;
                int b = (d >> 2) * G4STR + (k0 + q) * 4 + (d & 3);
                mma_tf32(acc[f], a0, a1, a2, a3, XsT[b], XsT[b + 16]);
            }
        }
    }

    // den: reduce across the quad (4 lanes share a row-pair), then across wc.
    den0 += __shfl_xor_sync(0xffffffffu, den0, 1);
    den0 += __shfl_xor_sync(0xffffffffu, den0, 2);
    den1 += __shfl_xor_sync(0xffffffffu, den1, 1);
    den1 += __shfl_xor_sync(0xffffffffu, den1, 2);
    __syncthreads();
    if (q == 0) {
        red[wc * 64 + 16 * wr + gid]     = den0;
        red[wc * 64 + 16 * wr + gid + 8] = den1;
    }
    __syncthreads();
    float rinv0 = 1.0f / (red[16 * wr + gid]     + red[64 + 16 * wr + gid]);
    float rinv1 = 1.0f / (red[16 * wr + gid + 8] + red[64 + 16 * wr + gid + 8]);

    float sq0 = 0.f, sq1 = 0.f;
    int r0 = mtile + 16 * wr + gid;
    #pragma unroll
    for (int f = 0; f < 16; f++) {
        int col = 128 * wc + 8 * f + 2 * q;
        float o0 = acc[f][0] * rinv0, o1 = acc[f][1] * rinv0;
        float o2 = acc[f][2] * rinv1, o3 = acc[f][3] * rinv1;
        sq0 += o0 * o0 + o1 * o1;
        sq1 += o2 * o2 + o3 * o3;
        *reinterpret_cast<float2*>(g_attn + r0 * D + col)       = make_float2(o0, o1);
        *reinterpret_cast<float2*>(g_attn + (r0 + 8) * D + col) = make_float2(o2, o3);
    }
    sq0 += __shfl_xor_sync(0xffffffffu, sq0, 1);
    sq0 += __shfl_xor_sync(0xffffffffu, sq0, 2);
    sq1 += __shfl_xor_sync(0xffffffffu, sq1, 1);
    sq1 += __shfl_xor_sync(0xffffffffu, sq1, 2);
    __syncthreads();   // all den reads done before red is reused
    if (q == 0) {
        red[wc * 64 + 16 * wr + gid]     = sq0;
        red[wc * 64 + 16 * wr + gid + 8] = sq1;
    }
    __syncthreads();
    if (tid < 64) g_sq[mtile + tid] = red[tid] + red[64 + tid];
}

// ---------------------------------------------------------------------------
// Kernel 3: feat[i] = mean_j exp(-max(sq_i + sq_j - 2*(attn_i . attn_j), 0))
// G = A A^T on mma tf32, fused RBF + row reduction.
// ---------------------------------------------------------------------------
__global__ void rbf_feat_kernel() {
    extern __shared__ uint32_t sm[];
    uint32_t* As  = sm;                  // [64][QSTR] resident attn rows
    uint32_t* Bs  = As + BM * QSTR;      // [64][QSTR] attn j-tile
    float*    sqj = (float*)(Bs + BM * QSTR);  // [64]
    float*    red = sqj + 64;                  // [2][64]

    int tid = threadIdx.x, lane = tid & 31, w = tid >> 5;
    int wr = w >> 1, wc = w & 1, gid = lane >> 2, q = lane & 3;
    int mtile = blockIdx.x * BM;

    stage_nat(g_attn, As, mtile, tid);
    float sqi0 = g_sq[mtile + 16 * wr + gid];
    float sqi1 = g_sq[mtile + 16 * wr + gid + 8];

    float fs0 = 0.f, fs1 = 0.f;
    int ar0 = (16 * wr + gid) * QSTR, ar1 = ar0 + 8 * QSTR;

    for (int jt = 0; jt < N_TOK / BN; jt++) {
        __syncthreads();
        int jb = jt * BN;
        stage_nat(g_attn, Bs, jb, tid);
        if (tid < 64) sqj[tid] = g_sq[jb + tid];
        __syncthreads();

        float cf[4][4] = {};
        #pragma unroll
        for (int ks = 0; ks < 32; ks++) {
            int k0 = ks * 8;
            uint32_t a0 = As[ar0 + k0 + q], a1 = As[ar1 + k0 + q];
            uint32_t a2 = As[ar0 + k0 + q + 4], a3 = As[ar1 + k0 + q + 4];
            #pragma unroll
            for (int f = 0; f < 4; f++) {
                int b = (32 * wc + 8 * f + gid) * QSTR + k0 + q;
                mma_tf32(cf[f], a0, a1, a2, a3, Bs[b], Bs[b + 4]);
            }
        }

        #pragma unroll
        for (int f = 0; f < 4; f++) {
            int col = 32 * wc + 8 * f + 2 * q;
            float sj0 = sqj[col], sj1 = sqj[col + 1];
            fs0 += __expf(-fmaxf(sqi0 + sj0 - 2.0f * cf[f][0], 0.0f));
            fs0 += __expf(-fmaxf(sqi0 + sj1 - 2.0f * cf[f][1], 0.0f));
            fs1 += __expf(-fmaxf(sqi1 + sj0 - 2.0f * cf[f][2], 0.0f));
            fs1 += __expf(-fmaxf(sqi1 + sj1 - 2.0f * cf[f][3], 0.0f));
        }
    }

    fs0 += __shfl_xor_sync(0xffffffffu, fs0, 1);
    fs0 += __shfl_xor_sync(0xffffffffu, fs0, 2);
    fs1 += __shfl_xor_sync(0xffffffffu, fs1, 1);
    fs1 += __shfl_xor_sync(0xffffffffu, fs1, 2);
    __syncthreads();
    if (q == 0) {
        red[wc * 64 + 16 * wr + gid]     = fs0;
        red[wc * 64 + 16 * wr + gid + 8] = fs1;
    }
    __syncthreads();
    if (tid < 64)
        g_feat[mtile + tid] = (red[tid] + red[64 + tid]) * (1.0f / (float)N_TOK);
}

// ---------------------------------------------------------------------------
// Kernel 4: MLP head
// ---------------------------------------------------------------------------
__global__ void mlp_kernel(const float* __restrict__ W1, const float* __restrict__ b1,
                           const float* __restrict__ W2, const float* __restrict__ b2,
                           float* __restrict__ out) {
    __shared__ float w1[64], bb1[64], w2[64];
    int tid = threadIdx.x;
    if (tid < 64) { w1[tid] = W1[tid]; bb1[tid] = b1[tid]; w2[tid] = W2[tid]; }
    __syncthreads();
    int i = blockIdx.x * blockDim.x + tid;
    if (i >= N_TOK) return;
    float f = g_feat[i];
    float a = b2[0];
    #pragma unroll
    for (int k2 = 0; k2 < 64; k2++) {
        float h = fmaf(f, w1[k2], bb1[k2]);
        a = fmaf(fmaxf(h, 0.0f), w2[k2], a);
    }
    out[i] = a;
}

// ---------------------------------------------------------------------------
extern "C" void kernel_launch(void* const* d_in, const int* in_sizes, int n_in,
                              void* d_out, int out_size) {
    const float* states = (const float*)d_in[0];
    const float* Wq     = (const float*)d_in[1];
    const float* Wk     = (const float*)d_in[2];
    const float* W1     = (const float*)d_in[3];
    const float* b1     = (const float*)d_in[4];
    const float* W2     = (const float*)d_in[5];
    const float* b2     = (const float*)d_in[6];
    float* out = (float*)d_out;
    (void)in_sizes; (void)n_in; (void)out_size;

    size_t smem_gemm  = (size_t)(2 * BM * QSTR) * 4;
    size_t smem_flash = (size_t)(2 * BM * QSTR + (D / 4) * G4STR + BM * ESTR + 128) * 4;
    size_t smem_rbf   = (size_t)(2 * BM * QSTR) * 4 + (64 + 128) * 4;

    (void)cudaFuncSetAttribute(gemm_qk_kernel,    cudaFuncAttributeMaxDynamicSharedMemorySize, (int)smem_gemm);
    (void)cudaFuncSetAttribute(flash_attn_kernel, cudaFuncAttributeMaxDynamicSharedMemorySize, (int)smem_flash);
    (void)cudaFuncSetAttribute(rbf_feat_kernel,   cudaFuncAttributeMaxDynamicSharedMemorySize, (int)smem_rbf);

    dim3 g1(D / BN, N_TOK / BM, 2);
    gemm_qk_kernel<<<g1, TPB, smem_gemm>>>(states, Wq, Wk);
    flash_attn_kernel<<<N_TOK / BM, TPB, smem_flash>>>(states);
    rbf_feat_kernel<<<N_TOK / BM, TPB, smem_rbf>>>();
    mlp_kernel<<<N_TOK / TPB, TPB>>>(W1, b1, W2, b2, out);
}

// round 6
// speedup vs baseline: 7.3207x; 2.4757x over previous
#include <cuda_runtime.h>
#include <cuda_bf16.h>
#include <math.h>
#include <stdint.h>

#define N_TOK 8192
#define D 256
#define BM 64
#define BN 64
#define TPB 256
#define KSTR 264   // bf16 stride for [64][256] tiles: 528B rows -> ldmatrix bank pattern 4r, conflict-free
#define ESTR 72    // bf16 stride for E tile [64][64]: 144B rows
#define NT (N_TOK / BN)

__device__ __align__(16) __nv_bfloat16 g_q[N_TOK * D];
__device__ __align__(16) __nv_bfloat16 g_k[N_TOK * D];
__device__ __align__(16) __nv_bfloat16 g_x[N_TOK * D];
__device__ __align__(16) __nv_bfloat16 g_attn[N_TOK * D];
__device__ float g_sq[N_TOK];
__device__ float g_feat[N_TOK];

__device__ __forceinline__ uint32_t smem_u32(const void* p) {
    return (uint32_t)__cvta_generic_to_shared(p);
}
__device__ __forceinline__ void ldmx4(uint32_t r[4], uint32_t addr) {
    asm volatile("ldmatrix.sync.aligned.m8n8.x4.shared.b16 {%0,%1,%2,%3}, [%4];"
                 : "=r"(r[0]), "=r"(r[1]), "=r"(r[2]), "=r"(r[3]) : "r"(addr));
}
__device__ __forceinline__ void ldmx4t(uint32_t r[4], uint32_t addr) {
    asm volatile("ldmatrix.sync.aligned.m8n8.x4.trans.shared.b16 {%0,%1,%2,%3}, [%4];"
                 : "=r"(r[0]), "=r"(r[1]), "=r"(r[2]), "=r"(r[3]) : "r"(addr));
}
__device__ __forceinline__ void mma_bf16(float* c, const uint32_t* a, uint32_t b0, uint32_t b1) {
    asm volatile(
        "mma.sync.aligned.m16n8k16.row.col.f32.bf16.bf16.f32 "
        "{%0,%1,%2,%3}, {%4,%5,%6,%7}, {%8,%9}, {%0,%1,%2,%3};"
        : "+f"(c[0]), "+f"(c[1]), "+f"(c[2]), "+f"(c[3])
        : "r"(a[0]), "r"(a[1]), "r"(a[2]), "r"(a[3]), "r"(b0), "r"(b1));
}
__device__ __forceinline__ uint32_t packbf(float x, float y) {
    __nv_bfloat162 p = __float22bfloat162_rn(make_float2(x, y));
    return *reinterpret_cast<uint32_t*>(&p);
}

// ---------------------------------------------------------------------------
// Kernel 0: states fp32 -> bf16 copy
// ---------------------------------------------------------------------------
__global__ void cvt_kernel(const float* __restrict__ x) {
    int i = blockIdx.x * blockDim.x + threadIdx.x;   // float4 index
    float4 t = reinterpret_cast<const float4*>(x)[i];
    uint2 u;
    u.x = packbf(t.x, t.y);
    u.y = packbf(t.z, t.w);
    reinterpret_cast<uint2*>(g_x)[i] = u;
}

// ---------------------------------------------------------------------------
// Kernel 1: q = states @ Wq, k = states @ Wk   (bf16 mma, blockIdx.z selects)
// ---------------------------------------------------------------------------
__global__ void gemm_qk_kernel(const float* __restrict__ x,
                               const float* __restrict__ Wq,
                               const float* __restrict__ Wk) {
    extern __shared__ char smraw[];
    __nv_bfloat16* Xs = (__nv_bfloat16*)smraw;        // [64][KSTR]
    __nv_bfloat16* Wg = Xs + BM * KSTR;               // [64][KSTR] : Wg[n][k] = W[k][ntile+n]

    const float* W = (blockIdx.z == 0) ? Wq : Wk;
    __nv_bfloat16* out = (blockIdx.z == 0) ? g_q : g_k;

    int mtile = blockIdx.y * BM;
    int ntile = blockIdx.x * BN;
    int tid = threadIdx.x, lane = tid & 31, w = tid >> 5;
    int wr = w >> 1, wc = w & 1, gid = lane >> 2, q = lane & 3;

    for (int v = tid; v < BM * (D / 4); v += TPB) {
        int m = v >> 6, c4 = v & 63;
        float4 t = reinterpret_cast<const float4*>(x + (mtile + m) * D)[c4];
        uint2 u;
        u.x = packbf(t.x, t.y);
        u.y = packbf(t.z, t.w);
        *reinterpret_cast<uint2*>(Xs + m * KSTR + c4 * 4) = u;
    }
    for (int v = tid; v < D * (BN / 4); v += TPB) {
        int kk = v >> 4, n4 = (v & 15) * 4;
        float4 t = *reinterpret_cast<const float4*>(W + kk * D + ntile + n4);
        Wg[(n4 + 0) * KSTR + kk] = __float2bfloat16(t.x);
        Wg[(n4 + 1) * KSTR + kk] = __float2bfloat16(t.y);
        Wg[(n4 + 2) * KSTR + kk] = __float2bfloat16(t.z);
        Wg[(n4 + 3) * KSTR + kk] = __float2bfloat16(t.w);
    }
    __syncthreads();

    uint32_t xsa = smem_u32(Xs), wga = smem_u32(Wg);
    uint32_t qa_base = ((16 * wr + (lane & 15)) * KSTR + 8 * (lane >> 4)) * 2;
    uint32_t kb_base = ((32 * wc + (lane & 7) + 8 * (lane >> 4)) * KSTR + 8 * ((lane >> 3) & 1)) * 2;

    float c[4][4] = {};
    #pragma unroll
    for (int ks = 0; ks < 16; ks++) {
        uint32_t a[4], b0[4], b1[4];
        ldmx4(a, xsa + qa_base + ks * 32);
        ldmx4(b0, wga + kb_base + ks * 32);
        ldmx4(b1, wga + kb_base + 16 * KSTR * 2 + ks * 32);
        mma_bf16(c[0], a, b0[0], b0[1]);
        mma_bf16(c[1], a, b0[2], b0[3]);
        mma_bf16(c[2], a, b1[0], b1[1]);
        mma_bf16(c[3], a, b1[2], b1[3]);
    }

    int r0 = mtile + 16 * wr + gid;
    #pragma unroll
    for (int f = 0; f < 4; f++) {
        int col = ntile + 32 * wc + 8 * f + 2 * q;
        *reinterpret_cast<uint32_t*>(out + r0 * D + col)       = packbf(c[f][0], c[f][1]);
        *reinterpret_cast<uint32_t*>(out + (r0 + 8) * D + col) = packbf(c[f][2], c[f][3]);
    }
}

// ---------------------------------------------------------------------------
// Kernel 2: flash attention, bf16 mma + ldmatrix + register-prefetch pipeline.
//   S = Q K^T -> E = exp(S/16) -> acc += E @ X, den += rowsum(E)
// Epilogue: attn = bf16(acc/den) stored; sq = ||bf16(attn)||^2 (consistent w/ RBF).
// ---------------------------------------------------------------------------
__global__ void flash_attn_kernel() {
    extern __shared__ char smraw[];
    __nv_bfloat16* Qs = (__nv_bfloat16*)smraw;   // [64][KSTR]
    __nv_bfloat16* Ks = Qs + BM * KSTR;          // [64][KSTR]
    __nv_bfloat16* Xs = Ks + BM * KSTR;          // [64][KSTR]
    __nv_bfloat16* Es = Xs + BM * KSTR;          // [64][ESTR]
    float* red = (float*)(Es + BM * ESTR);       // [2][64]

    int tid = threadIdx.x, lane = tid & 31, w = tid >> 5;
    int wr = w >> 1, wc = w & 1, gid = lane >> 2, q = lane & 3;
    int mtile = blockIdx.x * BM;

    const uint4* gq4 = reinterpret_cast<const uint4*>(g_q);
    const uint4* gk4 = reinterpret_cast<const uint4*>(g_k);
    const uint4* gx4 = reinterpret_cast<const uint4*>(g_x);

    // Stage resident Q tile (bf16 rows of 32 x uint4)
    #pragma unroll
    for (int i = 0; i < 8; i++) {
        uint4 t = gq4[(mtile + w + 8 * i) * 32 + lane];
        *((uint4*)(Qs + (w + 8 * i) * KSTR) + lane) = t;
    }

    uint32_t qsa = smem_u32(Qs), ksa = smem_u32(Ks), xsa = smem_u32(Xs), esa = smem_u32(Es);
    uint32_t qa_base = ((16 * wr + (lane & 15)) * KSTR + 8 * (lane >> 4)) * 2;
    uint32_t kb_base = ((32 * wc + (lane & 7) + 8 * (lane >> 4)) * KSTR + 8 * ((lane >> 3) & 1)) * 2;
    uint32_t ea_base = ((16 * wr + (lane & 15)) * ESTR + 8 * (lane >> 4)) * 2;
    uint32_t xb_base = ((lane & 15) * KSTR + 8 * (lane >> 4)) * 2;

    float acc[16][4];
    #pragma unroll
    for (int f = 0; f < 16; f++)
        acc[f][0] = acc[f][1] = acc[f][2] = acc[f][3] = 0.f;
    float den0 = 0.f, den1 = 0.f;

    // Prefetch tile 0 into registers
    uint4 pfk[8], pfx[8];
    #pragma unroll
    for (int i = 0; i < 8; i++) {
        pfk[i] = gk4[(w + 8 * i) * 32 + lane];
        pfx[i] = gx4[(w + 8 * i) * 32 + lane];
    }

    for (int jt = 0; jt < NT; jt++) {
        __syncthreads();   // previous iteration's Ks/Xs readers done
        #pragma unroll
        for (int i = 0; i < 8; i++) {
            *((uint4*)(Ks + (w + 8 * i) * KSTR) + lane) = pfk[i];
            *((uint4*)(Xs + (w + 8 * i) * KSTR) + lane) = pfx[i];
        }
        __syncthreads();
        if (jt + 1 < NT) {   // issue next tile's loads under the compute shadow
            int jb2 = (jt + 1) * BN;
            #pragma unroll
            for (int i = 0; i < 8; i++) {
                pfk[i] = gk4[(jb2 + w + 8 * i) * 32 + lane];
                pfx[i] = gx4[(jb2 + w + 8 * i) * 32 + lane];
            }
        }

        // Stage 1: S = Q @ K^T
        float cS[4][4] = {};
        #pragma unroll
        for (int ks = 0; ks < 16; ks++) {
            uint32_t a[4], b0[4], b1[4];
            ldmx4(a, qsa + qa_base + ks * 32);
            ldmx4(b0, ksa + kb_base + ks * 32);
            ldmx4(b1, ksa + kb_base + 16 * KSTR * 2 + ks * 32);
            mma_bf16(cS[0], a, b0[0], b0[1]);
            mma_bf16(cS[1], a, b0[2], b0[3]);
            mma_bf16(cS[2], a, b1[0], b1[1]);
            mma_bf16(cS[3], a, b1[2], b1[3]);
        }

        // E = exp(S/16): den in fp32, E stored bf16 for stage-2 A fragments
        #pragma unroll
        for (int f = 0; f < 4; f++) {
            float e0 = __expf(cS[f][0] * 0.0625f);
            float e1 = __expf(cS[f][1] * 0.0625f);
            float e2 = __expf(cS[f][2] * 0.0625f);
            float e3 = __expf(cS[f][3] * 0.0625f);
            den0 += e0 + e1; den1 += e2 + e3;
            int col = 32 * wc + 8 * f + 2 * q;
            *reinterpret_cast<uint32_t*>(Es + (16 * wr + gid) * ESTR + col)     = packbf(e0, e1);
            *reinterpret_cast<uint32_t*>(Es + (16 * wr + gid + 8) * ESTR + col) = packbf(e2, e3);
        }
        __syncthreads();

        // Stage 2: acc += E @ X   (B fragments via ldmatrix.trans on natural [j][d] Xs)
        #pragma unroll
        for (int ks = 0; ks < 4; ks++) {
            uint32_t a[4];
            ldmx4(a, esa + ea_base + ks * 32);
            #pragma unroll
            for (int u = 0; u < 8; u++) {
                uint32_t b[4];
                ldmx4t(b, xsa + xb_base + ks * (16 * KSTR * 2) + (128 * wc + 16 * u) * 2);
                mma_bf16(acc[2 * u],     a, b[0], b[1]);
                mma_bf16(acc[2 * u + 1], a, b[2], b[3]);
            }
        }
    }

    // den: reduce across quad lanes, then across wc via smem.
    den0 += __shfl_xor_sync(0xffffffffu, den0, 1);
    den0 += __shfl_xor_sync(0xffffffffu, den0, 2);
    den1 += __shfl_xor_sync(0xffffffffu, den1, 1);
    den1 += __shfl_xor_sync(0xffffffffu, den1, 2);
    __syncthreads();
    if (q == 0) {
        red[wc * 64 + 16 * wr + gid]     = den0;
        red[wc * 64 + 16 * wr + gid + 8] = den1;
    }
    __syncthreads();
    float rinv0 = 1.0f / (red[16 * wr + gid]     + red[64 + 16 * wr + gid]);
    float rinv1 = 1.0f / (red[16 * wr + gid + 8] + red[64 + 16 * wr + gid + 8]);

    // Normalize, round to bf16, store; sq from the ROUNDED values (RBF consistency).
    float sq0 = 0.f, sq1 = 0.f;
    int r0 = mtile + 16 * wr + gid;
    #pragma unroll
    for (int f = 0; f < 16; f++) {
        int col = 128 * wc + 8 * f + 2 * q;
        uint32_t p0 = packbf(acc[f][0] * rinv0, acc[f][1] * rinv0);
        uint32_t p1 = packbf(acc[f][2] * rinv1, acc[f][3] * rinv1);
        *reinterpret_cast<uint32_t*>(g_attn + r0 * D + col)       = p0;
        *reinterpret_cast<uint32_t*>(g_attn + (r0 + 8) * D + col) = p1;
        float2 v0 = __bfloat1622float2(*reinterpret_cast<__nv_bfloat162*>(&p0));
        float2 v1 = __bfloat1622float2(*reinterpret_cast<__nv_bfloat162*>(&p1));
        sq0 += v0.x * v0.x + v0.y * v0.y;
        sq1 += v1.x * v1.x + v1.y * v1.y;
    }
    sq0 += __shfl_xor_sync(0xffffffffu, sq0, 1);
    sq0 += __shfl_xor_sync(0xffffffffu, sq0, 2);
    sq1 += __shfl_xor_sync(0xffffffffu, sq1, 1);
    sq1 += __shfl_xor_sync(0xffffffffu, sq1, 2);
    __syncthreads();   // den reads done before red reuse
    if (q == 0) {
        red[wc * 64 + 16 * wr + gid]     = sq0;
        red[wc * 64 + 16 * wr + gid + 8] = sq1;
    }
    __syncthreads();
    if (tid < 64) g_sq[mtile + tid] = red[tid] + red[64 + tid];
}

// ---------------------------------------------------------------------------
// Kernel 3: feat[i] = mean_j exp(-max(sq_i + sq_j - 2*(attn_i . attn_j), 0))
// bf16 mma + ldmatrix + prefetch; fused RBF + row reduction.
// ---------------------------------------------------------------------------
__global__ void rbf_feat_kernel() {
    extern __shared__ char smraw[];
    __nv_bfloat16* As = (__nv_bfloat16*)smraw;   // [64][KSTR] resident attn rows
    __nv_bfloat16* Bs = As + BM * KSTR;          // [64][KSTR] j-tile
    float* sqj = (float*)(Bs + BM * KSTR);       // [64]
    float* red = sqj + 64;                       // [2][64]

    int tid = threadIdx.x, lane = tid & 31, w = tid >> 5;
    int wr = w >> 1, wc = w & 1, gid = lane >> 2, q = lane & 3;
    int mtile = blockIdx.x * BM;

    const uint4* ga4 = reinterpret_cast<const uint4*>(g_attn);
    #pragma unroll
    for (int i = 0; i < 8; i++) {
        uint4 t = ga4[(mtile + w + 8 * i) * 32 + lane];
        *((uint4*)(As + (w + 8 * i) * KSTR) + lane) = t;
    }

    uint32_t asa = smem_u32(As), bsa = smem_u32(Bs);
    uint32_t qa_base = ((16 * wr + (lane & 15)) * KSTR + 8 * (lane >> 4)) * 2;
    uint32_t kb_base = ((32 * wc + (lane & 7) + 8 * (lane >> 4)) * KSTR + 8 * ((lane >> 3) & 1)) * 2;

    float sqi0 = g_sq[mtile + 16 * wr + gid];
    float sqi1 = g_sq[mtile + 16 * wr + gid + 8];
    float fs0 = 0.f, fs1 = 0.f;

    uint4 pf[8];
    #pragma unroll
    for (int i = 0; i < 8; i++) pf[i] = ga4[(w + 8 * i) * 32 + lane];

    for (int jt = 0; jt < NT; jt++) {
        __syncthreads();
        #pragma unroll
        for (int i = 0; i < 8; i++)
            *((uint4*)(Bs + (w + 8 * i) * KSTR) + lane) = pf[i];
        if (tid < 64) sqj[tid] = g_sq[jt * BN + tid];
        __syncthreads();
        if (jt + 1 < NT) {
            int jb2 = (jt + 1) * BN;
            #pragma unroll
            for (int i = 0; i < 8; i++) pf[i] = ga4[(jb2 + w + 8 * i) * 32 + lane];
        }

        float cf[4][4] = {};
        #pragma unroll
        for (int ks = 0; ks < 16; ks++) {
            uint32_t a[4], b0[4], b1[4];
            ldmx4(a, asa + qa_base + ks * 32);
            ldmx4(b0, bsa + kb_base + ks * 32);
            ldmx4(b1, bsa + kb_base + 16 * KSTR * 2 + ks * 32);
            mma_bf16(cf[0], a, b0[0], b0[1]);
            mma_bf16(cf[1], a, b0[2], b0[3]);
            mma_bf16(cf[2], a, b1[0], b1[1]);
            mma_bf16(cf[3], a, b1[2], b1[3]);
        }

        #pragma unroll
        for (int f = 0; f < 4; f++) {
            int col = 32 * wc + 8 * f + 2 * q;
            float sj0 = sqj[col], sj1 = sqj[col + 1];
            fs0 += __expf(-fmaxf(sqi0 + sj0 - 2.0f * cf[f][0], 0.0f));
            fs0 += __expf(-fmaxf(sqi0 + sj1 - 2.0f * cf[f][1], 0.0f));
            fs1 += __expf(-fmaxf(sqi1 + sj0 - 2.0f * cf[f][2], 0.0f));
            fs1 += __expf(-fmaxf(sqi1 + sj1 - 2.0f * cf[f][3], 0.0f));
        }
    }

    fs0 += __shfl_xor_sync(0xffffffffu, fs0, 1);
    fs0 += __shfl_xor_sync(0xffffffffu, fs0, 2);
    fs1 += __shfl_xor_sync(0xffffffffu, fs1, 1);
    fs1 += __shfl_xor_sync(0xffffffffu, fs1, 2);
    __syncthreads();
    if (q == 0) {
        red[wc * 64 + 16 * wr + gid]     = fs0;
        red[wc * 64 + 16 * wr + gid + 8] = fs1;
    }
    __syncthreads();
    if (tid < 64)
        g_feat[mtile + tid] = (red[tid] + red[64 + tid]) * (1.0f / (float)N_TOK);
}

// ---------------------------------------------------------------------------
// Kernel 4: MLP head
// ---------------------------------------------------------------------------
__global__ void mlp_kernel(const float* __restrict__ W1, const float* __restrict__ b1,
                           const float* __restrict__ W2, const float* __restrict__ b2,
                           float* __restrict__ out) {
    __shared__ float w1[64], bb1[64], w2[64];
    int tid = threadIdx.x;
    if (tid < 64) { w1[tid] = W1[tid]; bb1[tid] = b1[tid]; w2[tid] = W2[tid]; }
    __syncthreads();
    int i = blockIdx.x * blockDim.x + tid;
    if (i >= N_TOK) return;
    float f = g_feat[i];
    float a = b2[0];
    #pragma unroll
    for (int k2 = 0; k2 < 64; k2++) {
        float h = fmaf(f, w1[k2], bb1[k2]);
        a = fmaf(fmaxf(h, 0.0f), w2[k2], a);
    }
    out[i] = a;
}

// ---------------------------------------------------------------------------
extern "C" void kernel_launch(void* const* d_in, const int* in_sizes, int n_in,
                              void* d_out, int out_size) {
    const float* states = (const float*)d_in[0];
    const float* Wq     = (const float*)d_in[1];
    const float* Wk     = (const float*)d_in[2];
    const float* W1     = (const float*)d_in[3];
    const float* b1     = (const float*)d_in[4];
    const float* W2     = (const float*)d_in[5];
    const float* b2     = (const float*)d_in[6];
    float* out = (float*)d_out;
    (void)in_sizes; (void)n_in; (void)out_size;

    size_t smem_qk    = (size_t)(2 * BM * KSTR) * 2;
    size_t smem_flash = (size_t)(3 * BM * KSTR + BM * ESTR) * 2 + 128 * 4;
    size_t smem_rbf   = (size_t)(2 * BM * KSTR) * 2 + (64 + 128) * 4;

    (void)cudaFuncSetAttribute(gemm_qk_kernel,    cudaFuncAttributeMaxDynamicSharedMemorySize, (int)smem_qk);
    (void)cudaFuncSetAttribute(flash_attn_kernel, cudaFuncAttributeMaxDynamicSharedMemorySize, (int)smem_flash);
    (void)cudaFuncSetAttribute(rbf_feat_kernel,   cudaFuncAttributeMaxDynamicSharedMemorySize, (int)smem_rbf);

    cvt_kernel<<<(N_TOK * D / 4) / TPB, TPB>>>(states);
    dim3 g1(D / BN, N_TOK / BM, 2);
    gemm_qk_kernel<<<g1, TPB, smem_qk>>>(states, Wq, Wk);
    flash_attn_kernel<<<N_TOK / BM, TPB, smem_flash>>>();
    rbf_feat_kernel<<<N_TOK / BM, TPB, smem_rbf>>>();
    mlp_kernel<<<N_TOK / TPB, TPB>>>(W1, b1, W2, b2, out);
}

// round 7
// speedup vs baseline: 8.4271x; 1.1511x over previous
#include <cuda_runtime.h>
#include <cuda_bf16.h>
#include <math.h>
#include <stdint.h>

#define N_TOK 8192
#define D 256
#define BM 64
#define BN 64
#define TPB 256
#define KSTR 264   // bf16 stride for [64][256] tiles: 528B rows -> ldmatrix bank pattern 4r, conflict-free
#define ESTR 72    // bf16 stride for E tile [64][64]
#define NT (N_TOK / BN)

// flash smem: Qs + 2xKs + 2xXs + Es + red
static_assert((5 * BM * KSTR + BM * ESTR) * 2 + 512 <= 232448, "flash smem");

__device__ __align__(16) __nv_bfloat16 g_q[N_TOK * D];
__device__ __align__(16) __nv_bfloat16 g_k[N_TOK * D];
__device__ __align__(16) __nv_bfloat16 g_x[N_TOK * D];
__device__ __align__(16) __nv_bfloat16 g_attn[N_TOK * D];
__device__ float g_sq[N_TOK];
__device__ float g_feat[N_TOK];

__device__ __forceinline__ uint32_t smem_u32(const void* p) {
    return (uint32_t)__cvta_generic_to_shared(p);
}
__device__ __forceinline__ void ldmx4(uint32_t r[4], uint32_t addr) {
    asm volatile("ldmatrix.sync.aligned.m8n8.x4.shared.b16 {%0,%1,%2,%3}, [%4];"
                 : "=r"(r[0]), "=r"(r[1]), "=r"(r[2]), "=r"(r[3]) : "r"(addr));
}
__device__ __forceinline__ void ldmx4t(uint32_t r[4], uint32_t addr) {
    asm volatile("ldmatrix.sync.aligned.m8n8.x4.trans.shared.b16 {%0,%1,%2,%3}, [%4];"
                 : "=r"(r[0]), "=r"(r[1]), "=r"(r[2]), "=r"(r[3]) : "r"(addr));
}
__device__ __forceinline__ void mma_bf16(float* c, const uint32_t* a, uint32_t b0, uint32_t b1) {
    asm volatile(
        "mma.sync.aligned.m16n8k16.row.col.f32.bf16.bf16.f32 "
        "{%0,%1,%2,%3}, {%4,%5,%6,%7}, {%8,%9}, {%0,%1,%2,%3};"
        : "+f"(c[0]), "+f"(c[1]), "+f"(c[2]), "+f"(c[3])
        : "r"(a[0]), "r"(a[1]), "r"(a[2]), "r"(a[3]), "r"(b0), "r"(b1));
}
__device__ __forceinline__ uint32_t packbf(float x, float y) {
    __nv_bfloat162 p = __float22bfloat162_rn(make_float2(x, y));
    return *reinterpret_cast<uint32_t*>(&p);
}
__device__ __forceinline__ void cp16(uint32_t dst, const void* src) {
    asm volatile("cp.async.cg.shared.global [%0], [%1], 16;" :: "r"(dst), "l"(src));
}
__device__ __forceinline__ void cp_commit() { asm volatile("cp.async.commit_group;"); }
template <int N> __device__ __forceinline__ void cp_wait() {
    asm volatile("cp.async.wait_group %0;" :: "n"(N));
}

// ---------------------------------------------------------------------------
// Kernel 0: states fp32 -> bf16 copy
// ---------------------------------------------------------------------------
__global__ void cvt_kernel(const float* __restrict__ x) {
    int i = blockIdx.x * blockDim.x + threadIdx.x;
    float4 t = reinterpret_cast<const float4*>(x)[i];
    uint2 u;
    u.x = packbf(t.x, t.y);
    u.y = packbf(t.z, t.w);
    reinterpret_cast<uint2*>(g_x)[i] = u;
}

// ---------------------------------------------------------------------------
// Kernel 1: q = states @ Wq, k = states @ Wk   (bf16 mma, blockIdx.z selects)
// ---------------------------------------------------------------------------
__global__ void gemm_qk_kernel(const float* __restrict__ x,
                               const float* __restrict__ Wq,
                               const float* __restrict__ Wk) {
    extern __shared__ char smraw[];
    __nv_bfloat16* Xs = (__nv_bfloat16*)smraw;        // [64][KSTR]
    __nv_bfloat16* Wg = Xs + BM * KSTR;               // [64][KSTR] : Wg[n][k] = W[k][ntile+n]

    const float* W = (blockIdx.z == 0) ? Wq : Wk;
    __nv_bfloat16* out = (blockIdx.z == 0) ? g_q : g_k;

    int mtile = blockIdx.y * BM;
    int ntile = blockIdx.x * BN;
    int tid = threadIdx.x, lane = tid & 31, w = tid >> 5;
    int wr = w >> 1, wc = w & 1, gid = lane >> 2, q = lane & 3;

    for (int v = tid; v < BM * (D / 4); v += TPB) {
        int m = v >> 6, c4 = v & 63;
        float4 t = reinterpret_cast<const float4*>(x + (mtile + m) * D)[c4];
        uint2 u;
        u.x = packbf(t.x, t.y);
        u.y = packbf(t.z, t.w);
        *reinterpret_cast<uint2*>(Xs + m * KSTR + c4 * 4) = u;
    }
    for (int v = tid; v < D * (BN / 4); v += TPB) {
        int kk = v >> 4, n4 = (v & 15) * 4;
        float4 t = *reinterpret_cast<const float4*>(W + kk * D + ntile + n4);
        Wg[(n4 + 0) * KSTR + kk] = __float2bfloat16(t.x);
        Wg[(n4 + 1) * KSTR + kk] = __float2bfloat16(t.y);
        Wg[(n4 + 2) * KSTR + kk] = __float2bfloat16(t.z);
        Wg[(n4 + 3) * KSTR + kk] = __float2bfloat16(t.w);
    }
    __syncthreads();

    uint32_t xsa = smem_u32(Xs), wga = smem_u32(Wg);
    uint32_t qa_base = ((16 * wr + (lane & 15)) * KSTR + 8 * (lane >> 4)) * 2;
    uint32_t kb_base = ((32 * wc + (lane & 7) + 8 * (lane >> 4)) * KSTR + 8 * ((lane >> 3) & 1)) * 2;

    float c[4][4] = {};
    #pragma unroll
    for (int ks = 0; ks < 16; ks++) {
        uint32_t a[4], b0[4], b1[4];
        ldmx4(a, xsa + qa_base + ks * 32);
        ldmx4(b0, wga + kb_base + ks * 32);
        ldmx4(b1, wga + kb_base + 16 * KSTR * 2 + ks * 32);
        mma_bf16(c[0], a, b0[0], b0[1]);
        mma_bf16(c[1], a, b0[2], b0[3]);
        mma_bf16(c[2], a, b1[0], b1[1]);
        mma_bf16(c[3], a, b1[2], b1[3]);
    }

    int r0 = mtile + 16 * wr + gid;
    #pragma unroll
    for (int f = 0; f < 4; f++) {
        int col = ntile + 32 * wc + 8 * f + 2 * q;
        *reinterpret_cast<uint32_t*>(out + r0 * D + col)       = packbf(c[f][0], c[f][1]);
        *reinterpret_cast<uint32_t*>(out + (r0 + 8) * D + col) = packbf(c[f][2], c[f][3]);
    }
}

// ---------------------------------------------------------------------------
// Kernel 2: flash attention. Q fragments register-resident; K/X double-buffered
// via cp.async; E via smem round-trip.
// ---------------------------------------------------------------------------
__global__ void __launch_bounds__(TPB, 1) flash_attn_kernel() {
    extern __shared__ char smraw[];
    __nv_bfloat16* Qs  = (__nv_bfloat16*)smraw;      // [64][KSTR]
    __nv_bfloat16* Ks0 = Qs + BM * KSTR;
    __nv_bfloat16* Ks1 = Ks0 + BM * KSTR;
    __nv_bfloat16* Xs0 = Ks1 + BM * KSTR;
    __nv_bfloat16* Xs1 = Xs0 + BM * KSTR;
    __nv_bfloat16* Es  = Xs1 + BM * KSTR;            // [64][ESTR]
    float* red = (float*)(Es + BM * ESTR);           // [2][64]

    int tid = threadIdx.x, lane = tid & 31, w = tid >> 5;
    int wr = w >> 1, wc = w & 1, gid = lane >> 2, q = lane & 3;
    int mtile = blockIdx.x * BM;

    uint32_t ksa[2] = {smem_u32(Ks0), smem_u32(Ks1)};
    uint32_t xsa[2] = {smem_u32(Xs0), smem_u32(Xs1)};
    uint32_t esa = smem_u32(Es);

    // Stage resident Q tile
    const uint4* gq4 = reinterpret_cast<const uint4*>(g_q);
    #pragma unroll
    for (int i = 0; i < 8; i++) {
        uint4 t = gq4[(mtile + w + 8 * i) * 32 + lane];
        *((uint4*)(Qs + (w + 8 * i) * KSTR) + lane) = t;
    }

    // Prologue: issue tile-0 K/X loads into buffer 0
    #pragma unroll
    for (int i = 0; i < 8; i++) {
        int idx = tid + i * TPB;
        int row = idx >> 5, c16 = idx & 31;
        cp16(ksa[0] + (row * KSTR + c16 * 8) * 2, g_k + row * D + c16 * 8);
        cp16(xsa[0] + (row * KSTR + c16 * 8) * 2, g_x + row * D + c16 * 8);
    }
    cp_commit();
    __syncthreads();   // Qs staged

    // Q fragments resident (64 regs)
    uint32_t qa = smem_u32(Qs) + ((16 * wr + (lane & 15)) * KSTR + 8 * (lane >> 4)) * 2;
    uint32_t qfrag[16][4];
    #pragma unroll
    for (int ks = 0; ks < 16; ks++) ldmx4(qfrag[ks], qa + ks * 32);

    uint32_t kb_off = ((32 * wc + (lane & 7) + 8 * (lane >> 4)) * KSTR + 8 * ((lane >> 3) & 1)) * 2;
    uint32_t ea_base = ((16 * wr + (lane & 15)) * ESTR + 8 * (lane >> 4)) * 2;
    uint32_t xb_off = ((lane & 15) * KSTR + 8 * (lane >> 4)) * 2;

    float acc[16][4];
    #pragma unroll
    for (int f = 0; f < 16; f++)
        acc[f][0] = acc[f][1] = acc[f][2] = acc[f][3] = 0.f;
    float den0 = 0.f, den1 = 0.f;

    for (int jt = 0; jt < NT; jt++) {
        int cur = jt & 1;
        __syncthreads();   // prior reads of buf[1-cur] and Es complete
        if (jt + 1 < NT) {
            int jb = (jt + 1) * BN;
            #pragma unroll
            for (int i = 0; i < 8; i++) {
                int idx = tid + i * TPB;
                int row = idx >> 5, c16 = idx & 31;
                cp16(ksa[1 - cur] + (row * KSTR + c16 * 8) * 2, g_k + (jb + row) * D + c16 * 8);
                cp16(xsa[1 - cur] + (row * KSTR + c16 * 8) * 2, g_x + (jb + row) * D + c16 * 8);
            }
            cp_commit();
            cp_wait<1>();
        } else {
            cp_wait<0>();
        }
        __syncthreads();   // buf[cur] visible to all warps

        // Stage 1: S = Q @ K^T  (A resident)
        float cS[4][4] = {};
        uint32_t kb = ksa[cur] + kb_off;
        #pragma unroll
        for (int ks = 0; ks < 16; ks++) {
            uint32_t b0[4], b1[4];
            ldmx4(b0, kb + ks * 32);
            ldmx4(b1, kb + 16 * KSTR * 2 + ks * 32);
            mma_bf16(cS[0], qfrag[ks], b0[0], b0[1]);
            mma_bf16(cS[1], qfrag[ks], b0[2], b0[3]);
            mma_bf16(cS[2], qfrag[ks], b1[0], b1[1]);
            mma_bf16(cS[3], qfrag[ks], b1[2], b1[3]);
        }

        // E = exp(S/16)
        #pragma unroll
        for (int f = 0; f < 4; f++) {
            float e0 = __expf(cS[f][0] * 0.0625f);
            float e1 = __expf(cS[f][1] * 0.0625f);
            float e2 = __expf(cS[f][2] * 0.0625f);
            float e3 = __expf(cS[f][3] * 0.0625f);
            den0 += e0 + e1; den1 += e2 + e3;
            int col = 32 * wc + 8 * f + 2 * q;
            *reinterpret_cast<uint32_t*>(Es + (16 * wr + gid) * ESTR + col)     = packbf(e0, e1);
            *reinterpret_cast<uint32_t*>(Es + (16 * wr + gid + 8) * ESTR + col) = packbf(e2, e3);
        }
        __syncthreads();

        // Stage 2: acc += E @ X
        #pragma unroll
        for (int ks = 0; ks < 4; ks++) {
            uint32_t a[4];
            ldmx4(a, esa + ea_base + ks * 32);
            #pragma unroll
            for (int u = 0; u < 8; u++) {
                uint32_t b[4];
                ldmx4t(b, xsa[cur] + xb_off + ks * (16 * KSTR * 2) + (128 * wc + 16 * u) * 2);
                mma_bf16(acc[2 * u],     a, b[0], b[1]);
                mma_bf16(acc[2 * u + 1], a, b[2], b[3]);
            }
        }
    }

    // den reduce: quad lanes then cross-wc via smem
    den0 += __shfl_xor_sync(0xffffffffu, den0, 1);
    den0 += __shfl_xor_sync(0xffffffffu, den0, 2);
    den1 += __shfl_xor_sync(0xffffffffu, den1, 1);
    den1 += __shfl_xor_sync(0xffffffffu, den1, 2);
    __syncthreads();
    if (q == 0) {
        red[wc * 64 + 16 * wr + gid]     = den0;
        red[wc * 64 + 16 * wr + gid + 8] = den1;
    }
    __syncthreads();
    float rinv0 = 1.0f / (red[16 * wr + gid]     + red[64 + 16 * wr + gid]);
    float rinv1 = 1.0f / (red[16 * wr + gid + 8] + red[64 + 16 * wr + gid + 8]);

    float sq0 = 0.f, sq1 = 0.f;
    int r0 = mtile + 16 * wr + gid;
    #pragma unroll
    for (int f = 0; f < 16; f++) {
        int col = 128 * wc + 8 * f + 2 * q;
        uint32_t p0 = packbf(acc[f][0] * rinv0, acc[f][1] * rinv0);
        uint32_t p1 = packbf(acc[f][2] * rinv1, acc[f][3] * rinv1);
        *reinterpret_cast<uint32_t*>(g_attn + r0 * D + col)       = p0;
        *reinterpret_cast<uint32_t*>(g_attn + (r0 + 8) * D + col) = p1;
        float2 v0 = __bfloat1622float2(*reinterpret_cast<__nv_bfloat162*>(&p0));
        float2 v1 = __bfloat1622float2(*reinterpret_cast<__nv_bfloat162*>(&p1));
        sq0 += v0.x * v0.x + v0.y * v0.y;
        sq1 += v1.x * v1.x + v1.y * v1.y;
    }
    sq0 += __shfl_xor_sync(0xffffffffu, sq0, 1);
    sq0 += __shfl_xor_sync(0xffffffffu, sq0, 2);
    sq1 += __shfl_xor_sync(0xffffffffu, sq1, 1);
    sq1 += __shfl_xor_sync(0xffffffffu, sq1, 2);
    __syncthreads();
    if (q == 0) {
        red[wc * 64 + 16 * wr + gid]     = sq0;
        red[wc * 64 + 16 * wr + gid + 8] = sq1;
    }
    __syncthreads();
    if (tid < 64) g_sq[mtile + tid] = red[tid] + red[64 + tid];
}

// ---------------------------------------------------------------------------
// Kernel 3: RBF stage, restructured: warps own 32 rows x 16 cols; the full
// A operand (32 rows x K=256) is register-resident (128 regs, loaded once) ->
// per tile per warp: 16 ldmatrix (B only) vs 64 mma.
// ---------------------------------------------------------------------------
__global__ void __launch_bounds__(TPB, 1) rbf_feat_kernel() {
    extern __shared__ char smraw[];
    __nv_bfloat16* As = (__nv_bfloat16*)smraw;   // [64][KSTR] resident attn rows
    __nv_bfloat16* Bs = As + BM * KSTR;          // [64][KSTR] j-tile
    float* sqj = (float*)(Bs + BM * KSTR);       // [64]
    float* red = sqj + 64;                       // [4][64]

    int tid = threadIdx.x, lane = tid & 31, w = tid >> 5;
    int wr = w >> 2, wc = w & 3, gid = lane >> 2, q = lane & 3;
    int mtile = blockIdx.x * BM;

    const uint4* ga4 = reinterpret_cast<const uint4*>(g_attn);
    #pragma unroll
    for (int i = 0; i < 8; i++) {
        uint4 t = ga4[(mtile + w + 8 * i) * 32 + lane];
        *((uint4*)(As + (w + 8 * i) * KSTR) + lane) = t;
    }
    __syncthreads();

    // A fragments resident: rows 32*wr + 16*g + {0..15}, all K.  128 regs.
    uint32_t aa0 = smem_u32(As) + ((32 * wr + (lane & 15)) * KSTR + 8 * (lane >> 4)) * 2;
    uint32_t afrag[16][2][4];
    #pragma unroll
    for (int ks = 0; ks < 16; ks++) {
        ldmx4(afrag[ks][0], aa0 + ks * 32);
        ldmx4(afrag[ks][1], aa0 + 16 * KSTR * 2 + ks * 32);
    }

    uint32_t kb = smem_u32(Bs) +
        ((16 * wc + (lane & 7) + 8 * (lane >> 4)) * KSTR + 8 * ((lane >> 3) & 1)) * 2;

    float sqi[2][2], fs[2][2] = {};
    #pragma unroll
    for (int g = 0; g < 2; g++) {
        sqi[g][0] = g_sq[mtile + 32 * wr + 16 * g + gid];
        sqi[g][1] = g_sq[mtile + 32 * wr + 16 * g + gid + 8];
    }

    uint4 pf[8];
    #pragma unroll
    for (int i = 0; i < 8; i++) pf[i] = ga4[(w + 8 * i) * 32 + lane];

    for (int jt = 0; jt < NT; jt++) {
        __syncthreads();
        #pragma unroll
        for (int i = 0; i < 8; i++)
            *((uint4*)(Bs + (w + 8 * i) * KSTR) + lane) = pf[i];
        if (tid < 64) sqj[tid] = g_sq[jt * BN + tid];
        __syncthreads();
        if (jt + 1 < NT) {
            int jb2 = (jt + 1) * BN;
            #pragma unroll
            for (int i = 0; i < 8; i++) pf[i] = ga4[(jb2 + w + 8 * i) * 32 + lane];
        }

        float cf[2][2][4] = {};
        #pragma unroll
        for (int ks = 0; ks < 16; ks++) {
            uint32_t b[4];
            ldmx4(b, kb + ks * 32);
            mma_bf16(cf[0][0], afrag[ks][0], b[0], b[1]);
            mma_bf16(cf[0][1], afrag[ks][0], b[2], b[3]);
            mma_bf16(cf[1][0], afrag[ks][1], b[0], b[1]);
            mma_bf16(cf[1][1], afrag[ks][1], b[2], b[3]);
        }

        #pragma unroll
        for (int g = 0; g < 2; g++) {
            #pragma unroll
            for (int c = 0; c < 2; c++) {
                int col = 16 * wc + 8 * c + 2 * q;
                float sj0 = sqj[col], sj1 = sqj[col + 1];
                fs[g][0] += __expf(-fmaxf(sqi[g][0] + sj0 - 2.0f * cf[g][c][0], 0.0f));
                fs[g][0] += __expf(-fmaxf(sqi[g][0] + sj1 - 2.0f * cf[g][c][1], 0.0f));
                fs[g][1] += __expf(-fmaxf(sqi[g][1] + sj0 - 2.0f * cf[g][c][2], 0.0f));
                fs[g][1] += __expf(-fmaxf(sqi[g][1] + sj1 - 2.0f * cf[g][c][3], 0.0f));
            }
        }
    }

    #pragma unroll
    for (int g = 0; g < 2; g++) {
        #pragma unroll
        for (int h = 0; h < 2; h++) {
            fs[g][h] += __shfl_xor_sync(0xffffffffu, fs[g][h], 1);
            fs[g][h] += __shfl_xor_sync(0xffffffffu, fs[g][h], 2);
        }
    }
    __syncthreads();
    if (q == 0) {
        #pragma unroll
        for (int g = 0; g < 2; g++) {
            red[wc * 64 + 32 * wr + 16 * g + gid]     = fs[g][0];
            red[wc * 64 + 32 * wr + 16 * g + gid + 8] = fs[g][1];
        }
    }
    __syncthreads();
    if (tid < 64)
        g_feat[mtile + tid] = (red[tid] + red[64 + tid] + red[128 + tid] + red[192 + tid])
                              * (1.0f / (float)N_TOK);
}

// ---------------------------------------------------------------------------
// Kernel 4: MLP head
// ---------------------------------------------------------------------------
__global__ void mlp_kernel(const float* __restrict__ W1, const float* __restrict__ b1,
                           const float* __restrict__ W2, const float* __restrict__ b2,
                           float* __restrict__ out) {
    __shared__ float w1[64], bb1[64], w2[64];
    int tid = threadIdx.x;
    if (tid < 64) { w1[tid] = W1[tid]; bb1[tid] = b1[tid]; w2[tid] = W2[tid]; }
    __syncthreads();
    int i = blockIdx.x * blockDim.x + tid;
    if (i >= N_TOK) return;
    float f = g_feat[i];
    float a = b2[0];
    #pragma unroll
    for (int k2 = 0; k2 < 64; k2++) {
        float h = fmaf(f, w1[k2], bb1[k2]);
        a = fmaf(fmaxf(h, 0.0f), w2[k2], a);
    }
    out[i] = a;
}

// ---------------------------------------------------------------------------
extern "C" void kernel_launch(void* const* d_in, const int* in_sizes, int n_in,
                              void* d_out, int out_size) {
    const float* states = (const float*)d_in[0];
    const float* Wq     = (const float*)d_in[1];
    const float* Wk     = (const float*)d_in[2];
    const float* W1     = (const float*)d_in[3];
    const float* b1     = (const float*)d_in[4];
    const float* W2     = (const float*)d_in[5];
    const float* b2     = (const float*)d_in[6];
    float* out = (float*)d_out;
    (void)in_sizes; (void)n_in; (void)out_size;

    size_t smem_qk    = (size_t)(2 * BM * KSTR) * 2;
    size_t smem_flash = (size_t)(5 * BM * KSTR + BM * ESTR) * 2 + 512;
    size_t smem_rbf   = (size_t)(2 * BM * KSTR) * 2 + (64 + 256) * 4;

    (void)cudaFuncSetAttribute(gemm_qk_kernel,    cudaFuncAttributeMaxDynamicSharedMemorySize, (int)smem_qk);
    (void)cudaFuncSetAttribute(flash_attn_kernel, cudaFuncAttributeMaxDynamicSharedMemorySize, (int)smem_flash);
    (void)cudaFuncSetAttribute(rbf_feat_kernel,   cudaFuncAttributeMaxDynamicSharedMemorySize, (int)smem_rbf);

    cvt_kernel<<<(N_TOK * D / 4) / TPB, TPB>>>(states);
    dim3 g1(D / BN, N_TOK / BM, 2);
    gemm_qk_kernel<<<g1, TPB, smem_qk>>>(states, Wq, Wk);
    flash_attn_kernel<<<N_TOK / BM, TPB, smem_flash>>>();
    rbf_feat_kernel<<<N_TOK / BM, TPB, smem_rbf>>>();
    mlp_kernel<<<N_TOK / TPB, TPB>>>(W1, b1, W2, b2, out);
}